// round 11
// baseline (speedup 1.0000x reference)
#include <cuda_runtime.h>
#include <cstdint>

#define N_NODES 50000
#define N_EDGES 800000
#define NODE_DIM 128
#define IN_CH 64
#define OUT_CH 16
#define N_GRAPHS 512
#define N_LAYERS 5

#define SCAN_CHUNK 256
#define N_CHUNKS ((N_NODES + SCAN_CHUNK - 1) / SCAN_CHUNK)   // 196

// ---------------- scratch (device globals; 16B-aligned) ----------------------
__device__ __align__(16) float d_z0[N_NODES * IN_CH];   // ping
__device__ __align__(16) float d_z1[N_NODES * IN_CH];   // pong
__device__ __align__(16) double d_bnacc[N_LAYERS * 2 * IN_CH];
__device__ __align__(16) float d_g[N_GRAPHS * IN_CH];
__device__ int d_deg[N_NODES];
__device__ int d_rowptr[N_NODES + 1];
__device__ int d_cursor[N_NODES];
__device__ int d_csrsrc[N_EDGES];
__device__ int d_blocksum[N_CHUNKS];
__device__ int d_idx64;

__device__ __forceinline__ int load_idx(const void* p, long long i) {
    if (d_idx64) return (int)((const long long*)p)[i];
    return ((const int*)p)[i];
}

// ---------------- zero init + dtype sniff (merged) ---------------------------
__global__ void zero_detect_kernel(const unsigned int* __restrict__ ei_words) {
    int i = blockIdx.x * blockDim.x + threadIdx.x;
    if (blockIdx.x == 0) {
        __shared__ int any_nonzero;
        if (threadIdx.x == 0) any_nonzero = 0;
        __syncthreads();
        unsigned w = ei_words[threadIdx.x * 2 + 1];
        if (w != 0u) atomicOr(&any_nonzero, 1);
        __syncthreads();
        if (threadIdx.x == 0) d_idx64 = (any_nonzero == 0) ? 1 : 0;
    }
    if (i < N_NODES) d_deg[i] = 0;
    if (i < N_GRAPHS * IN_CH) d_g[i] = 0.0f;
    if (i < N_LAYERS * 2 * IN_CH) d_bnacc[i] = 0.0;
}

// ---------------- CSR build --------------------------------------------------
__global__ void count_kernel(const void* __restrict__ ei) {
    int e = blockIdx.x * blockDim.x + threadIdx.x;
    if (e >= N_EDGES) return;
    int dst = load_idx(ei, (long long)N_EDGES + e);
    atomicAdd(&d_deg[dst], 1);
}

__global__ void scan1_kernel() {
    __shared__ int wsum[8];
    const int t = threadIdx.x, lane = t & 31, w = t >> 5;
    int i = blockIdx.x * SCAN_CHUNK + t;
    int v = (i < N_NODES) ? d_deg[i] : 0;
    int x = v;
#pragma unroll
    for (int d = 1; d < 32; d <<= 1) x += __shfl_xor_sync(0xFFFFFFFFu, x, d);
    if (lane == 0) wsum[w] = x;
    __syncthreads();
    if (t == 0) {
        int s = 0;
#pragma unroll
        for (int j = 0; j < 8; j++) s += wsum[j];
        d_blocksum[blockIdx.x] = s;
    }
}

// merged pass 2+3: every block scans the 196 partials, then its own chunk
__global__ void scan23_kernel() {
    __shared__ int sh[N_CHUNKS];
    __shared__ int wsum[8];
    const int t = threadIdx.x, lane = t & 31, w = t >> 5;
    if (t < N_CHUNKS) sh[t] = d_blocksum[t];
    __syncthreads();
    for (int d = 1; d < N_CHUNKS; d <<= 1) {
        int x = 0;
        if (t < N_CHUNKS && t >= d) x = sh[t - d];
        __syncthreads();
        if (t < N_CHUNKS && t >= d) sh[t] += x;
        __syncthreads();
    }
    const int chunk_off = (blockIdx.x > 0) ? sh[blockIdx.x - 1] : 0;
    if (blockIdx.x == 0 && t == 0) d_rowptr[N_NODES] = N_EDGES;

    int i = blockIdx.x * SCAN_CHUNK + t;
    int v = (i < N_NODES) ? d_deg[i] : 0;
    int x = v;
#pragma unroll
    for (int d = 1; d < 32; d <<= 1) {
        int y = __shfl_up_sync(0xFFFFFFFFu, x, d);
        if (lane >= d) x += y;
    }
    if (lane == 31) wsum[w] = x;
    __syncthreads();
    if (w == 0 && lane < 8) {
        int y = wsum[lane];
#pragma unroll
        for (int d = 1; d < 8; d <<= 1) {
            int z = __shfl_up_sync(0xFFu, y, d);
            if (lane >= d) y += z;
        }
        wsum[lane] = y;
    }
    __syncthreads();
    int excl = chunk_off + (w > 0 ? wsum[w - 1] : 0) + x - v;
    if (i < N_NODES) { d_rowptr[i] = excl; d_cursor[i] = excl; }
}

__global__ void fill_kernel(const void* __restrict__ ei) {
    int e = blockIdx.x * blockDim.x + threadIdx.x;
    if (e >= N_EDGES) return;
    int src = load_idx(ei, e);
    int dst = load_idx(ei, (long long)N_EDGES + e);
    int pos = atomicAdd(&d_cursor[dst], 1);
    d_csrsrc[pos] = src;
}

// =============================================================================
// mma.sync tf32 split-precision GEMM machinery
// =============================================================================
__device__ __forceinline__ void mma8(float* d, const uint32_t* a, const uint32_t* b) {
    asm volatile(
        "mma.sync.aligned.m16n8k8.row.col.f32.tf32.tf32.f32 "
        "{%0,%1,%2,%3}, {%4,%5,%6,%7}, {%8,%9}, {%0,%1,%2,%3};"
        : "+f"(d[0]), "+f"(d[1]), "+f"(d[2]), "+f"(d[3])
        : "r"(a[0]), "r"(a[1]), "r"(a[2]), "r"(a[3]), "r"(b[0]), "r"(b[1]));
}
__device__ __forceinline__ void split1(float x, uint32_t& hi, uint32_t& lo) {
    uint32_t h = __float_as_uint(x) & 0xFFFFE000u;
    hi = h;
    lo = __float_as_uint(x - __uint_as_float(h));
}

// smem (floats): As 128x68, Ws 64x68, Wb 64x68, b1s/b2s/ssum/ssq/s_s/s_b 64 each
#define F_AS   0
#define F_WS   8704
#define F_WB   13056
#define F_B1   17408
#define F_B2   17472
#define F_SS   17536
#define F_SQ   17600
#define F_BNS  17664
#define F_BNB  17728
#define SMEM_MMA (17792 * 4)

// ---------------- encoder: z = x @ enc_W + enc_b (dense A, K=128) ------------
__global__ void __launch_bounds__(256)
enc_mma(const float* __restrict__ A, const float* __restrict__ W1g,
        const float* __restrict__ b1, float* __restrict__ out)
{
    extern __shared__ __align__(16) float sm[];
    float* As  = sm + F_AS;
    float* Ws  = sm + F_WS;
    float* b1s = sm + F_B1;

    const int tid = threadIdx.x, lane = tid & 31, wid = tid >> 5;
    const int q = lane >> 2, t4 = lane & 3;
    const int m0 = (wid & 3) * 32, n0 = (wid >> 2) * 32;
    const int row0 = blockIdx.x * 128;

    if (tid < 64) b1s[tid] = b1[tid];

    float acc[2][4][4];
#pragma unroll
    for (int i = 0; i < 2; i++)
#pragma unroll
        for (int j = 0; j < 4; j++)
#pragma unroll
            for (int r = 0; r < 4; r++) acc[i][j][r] = 0.f;

    for (int kc = 0; kc < 2; kc++) {
        if (kc) __syncthreads();
#pragma unroll
        for (int i = 0; i < 8; i++) {
            int f = tid + i * 256;
            int r = f >> 4, c4 = f & 15;
            int gr = row0 + r;
            float4 v = make_float4(0.f, 0.f, 0.f, 0.f);
            if (gr < N_NODES)
                v = *(const float4*)(A + (size_t)gr * 128 + kc * 64 + c4 * 4);
            *(float4*)(As + r * 68 + c4 * 4) = v;
        }
#pragma unroll
        for (int i = 0; i < 4; i++) {
            int f = tid + i * 256;
            int k = f >> 4, c4 = f & 15;
            *(float4*)(Ws + k * 68 + c4 * 4) =
                *(const float4*)(W1g + (size_t)(kc * 64 + k) * 64 + c4 * 4);
        }
        __syncthreads();
#pragma unroll
        for (int ks = 0; ks < 8; ks++) {
            uint32_t AH[2][4], AL[2][4];
#pragma unroll
            for (int i = 0; i < 2; i++) {
                const float* ap = As + (m0 + 16 * i + q) * 68 + ks * 8 + t4;
                split1(ap[0],          AH[i][0], AL[i][0]);
                split1(ap[8 * 68],     AH[i][1], AL[i][1]);
                split1(ap[4],          AH[i][2], AL[i][2]);
                split1(ap[8 * 68 + 4], AH[i][3], AL[i][3]);
            }
            uint32_t BH[4][2], BL[4][2];
#pragma unroll
            for (int j = 0; j < 4; j++) {
                const float* bp = Ws + (ks * 8 + t4) * 68 + n0 + 8 * j + q;
                split1(bp[0],      BH[j][0], BL[j][0]);
                split1(bp[4 * 68], BH[j][1], BL[j][1]);
            }
#pragma unroll
            for (int i = 0; i < 2; i++)
#pragma unroll
                for (int j = 0; j < 4; j++) {
                    mma8(acc[i][j], AH[i], BH[j]);
                    mma8(acc[i][j], AL[i], BH[j]);
                    mma8(acc[i][j], AH[i], BL[j]);
                }
        }
    }
    __syncthreads();
#pragma unroll
    for (int i = 0; i < 2; i++)
#pragma unroll
        for (int j = 0; j < 4; j++) {
            int c = n0 + 8 * j + 2 * t4;
            int r0 = m0 + 16 * i + q;
            *(float2*)(As + r0 * 68 + c) =
                make_float2(acc[i][j][0] + b1s[c], acc[i][j][1] + b1s[c + 1]);
            *(float2*)(As + (r0 + 8) * 68 + c) =
                make_float2(acc[i][j][2] + b1s[c], acc[i][j][3] + b1s[c + 1]);
        }
    __syncthreads();
#pragma unroll
    for (int i = 0; i < 8; i++) {
        int f = tid + i * 256;
        int r = f >> 4, c4 = f & 15;
        if (row0 + r < N_NODES)
            *(float4*)(out + (size_t)(row0 + r) * 64 + c4 * 4) =
                *(const float4*)(As + r * 68 + c4 * 4);
    }
}

// ---------------- fused GIN layer: gather(+BN) -> MLP(2 GEMMs) -> zout -------
// zin and zout MUST be different buffers (gather reads arbitrary rows of zin).
template<bool BN>
__global__ void __launch_bounds__(256)
gin_mma(const float* __restrict__ zin, const float* __restrict__ W1g,
        const float* __restrict__ b1, const float* __restrict__ W2g,
        const float* __restrict__ b2, float* __restrict__ out,
        const double* __restrict__ accprev, const float* __restrict__ gamma,
        const float* __restrict__ beta, double* __restrict__ bnacc)
{
    extern __shared__ __align__(16) float sm[];
    float* As  = sm + F_AS;
    float* Ws  = sm + F_WS;
    float* Wb  = sm + F_WB;
    float* b1s = sm + F_B1;
    float* b2s = sm + F_B2;
    float* ssum = sm + F_SS;
    float* ssq  = sm + F_SQ;
    float* s_s = sm + F_BNS;
    float* s_b = sm + F_BNB;

    const int tid = threadIdx.x, lane = tid & 31, wid = tid >> 5;
    const int q = lane >> 2, t4 = lane & 3;
    const int m0 = (wid & 3) * 32, n0 = (wid >> 2) * 32;
    const int row0 = blockIdx.x * 128;

    if (tid < 64) {
        b1s[tid] = b1[tid];
        b2s[tid] = b2[tid];
        ssum[tid] = 0.f;
        ssq[tid] = 0.f;
        if (BN) {
            double sum = accprev[tid], sq = accprev[64 + tid];
            float mean = (float)(sum / (double)N_NODES);
            float var = (float)(sq / (double)N_NODES) - mean * mean;
            float sc = gamma[tid] * rsqrtf(var + 1e-5f);
            s_s[tid] = sc;
            s_b[tid] = beta[tid] - mean * sc;
        }
    }
    // stage W1 + W2
#pragma unroll
    for (int i = 0; i < 4; i++) {
        int f = tid + i * 256;
        int k = f >> 4, c4 = f & 15;
        *(float4*)(Ws + k * 68 + c4 * 4) = *(const float4*)(W1g + (size_t)k * 64 + c4 * 4);
        *(float4*)(Wb + k * 68 + c4 * 4) = *(const float4*)(W2g + (size_t)k * 64 + c4 * 4);
    }
    __syncthreads();   // s_s/s_b ready for gather

    // ---- gather prologue: As[r] = BN(z)[node] + sum_{src->node} BN(z)[src] --
    // unroll-4 with 4 independent loads in flight + dual accumulator chains
    {
        const int c0 = lane * 2;
        const float sx = BN ? s_s[c0] : 1.f, sy = BN ? s_s[c0 + 1] : 1.f;
        const float bx = BN ? s_b[c0] : 0.f, by = BN ? s_b[c0 + 1] : 0.f;
#pragma unroll
        for (int i = 0; i < 16; i++) {
            int r = i * 8 + wid;
            int node = row0 + r;
            float ax0 = 0.f, ay0 = 0.f, ax1 = 0.f, ay1 = 0.f;
            if (node < N_NODES) {
                float2 v = *(const float2*)(zin + (size_t)node * 64 + c0);
                ax0 = v.x * sx + bx;
                ay0 = v.y * sy + by;
                int j = d_rowptr[node];
                const int r1 = d_rowptr[node + 1];
                for (; j + 3 < r1; j += 4) {
                    int i0 = d_csrsrc[j + 0];
                    int i1 = d_csrsrc[j + 1];
                    int i2 = d_csrsrc[j + 2];
                    int i3 = d_csrsrc[j + 3];
                    float2 v0 = *(const float2*)(zin + (size_t)i0 * 64 + c0);
                    float2 v1 = *(const float2*)(zin + (size_t)i1 * 64 + c0);
                    float2 v2 = *(const float2*)(zin + (size_t)i2 * 64 + c0);
                    float2 v3 = *(const float2*)(zin + (size_t)i3 * 64 + c0);
                    ax0 += v0.x * sx + bx; ay0 += v0.y * sy + by;
                    ax1 += v1.x * sx + bx; ay1 += v1.y * sy + by;
                    ax0 += v2.x * sx + bx; ay0 += v2.y * sy + by;
                    ax1 += v3.x * sx + bx; ay1 += v3.y * sy + by;
                }
                if (j + 1 < r1) {
                    int i0 = d_csrsrc[j], i1 = d_csrsrc[j + 1];
                    float2 v0 = *(const float2*)(zin + (size_t)i0 * 64 + c0);
                    float2 v1 = *(const float2*)(zin + (size_t)i1 * 64 + c0);
                    ax0 += v0.x * sx + bx; ay0 += v0.y * sy + by;
                    ax1 += v1.x * sx + bx; ay1 += v1.y * sy + by;
                    j += 2;
                }
                if (j < r1) {
                    int i0 = d_csrsrc[j];
                    float2 v0 = *(const float2*)(zin + (size_t)i0 * 64 + c0);
                    ax0 += v0.x * sx + bx; ay0 += v0.y * sy + by;
                }
            }
            *(float2*)(As + r * 68 + c0) = make_float2(ax0 + ax1, ay0 + ay1);
        }
    }
    __syncthreads();

    // ---- stage 1: D = A @ W1 ----
    float acc[2][4][4];
#pragma unroll
    for (int i = 0; i < 2; i++)
#pragma unroll
        for (int j = 0; j < 4; j++)
#pragma unroll
            for (int r = 0; r < 4; r++) acc[i][j][r] = 0.f;

#pragma unroll
    for (int ks = 0; ks < 8; ks++) {
        uint32_t AH[2][4], AL[2][4];
#pragma unroll
        for (int i = 0; i < 2; i++) {
            const float* ap = As + (m0 + 16 * i + q) * 68 + ks * 8 + t4;
            split1(ap[0],          AH[i][0], AL[i][0]);
            split1(ap[8 * 68],     AH[i][1], AL[i][1]);
            split1(ap[4],          AH[i][2], AL[i][2]);
            split1(ap[8 * 68 + 4], AH[i][3], AL[i][3]);
        }
        uint32_t BH[4][2], BL[4][2];
#pragma unroll
        for (int j = 0; j < 4; j++) {
            const float* bp = Ws + (ks * 8 + t4) * 68 + n0 + 8 * j + q;
            split1(bp[0],      BH[j][0], BL[j][0]);
            split1(bp[4 * 68], BH[j][1], BL[j][1]);
        }
#pragma unroll
        for (int i = 0; i < 2; i++)
#pragma unroll
            for (int j = 0; j < 4; j++) {
                mma8(acc[i][j], AH[i], BH[j]);
                mma8(acc[i][j], AL[i], BH[j]);
                mma8(acc[i][j], AH[i], BL[j]);
            }
    }

    // T = relu(D + b1) -> As
    __syncthreads();
#pragma unroll
    for (int i = 0; i < 2; i++)
#pragma unroll
        for (int j = 0; j < 4; j++) {
            int c = n0 + 8 * j + 2 * t4;
            int r0 = m0 + 16 * i + q;
            *(float2*)(As + r0 * 68 + c) =
                make_float2(fmaxf(acc[i][j][0] + b1s[c], 0.f),
                            fmaxf(acc[i][j][1] + b1s[c + 1], 0.f));
            *(float2*)(As + (r0 + 8) * 68 + c) =
                make_float2(fmaxf(acc[i][j][2] + b1s[c], 0.f),
                            fmaxf(acc[i][j][3] + b1s[c + 1], 0.f));
        }
    __syncthreads();

    // ---- stage 2: D2 = T @ W2 ----
    float ac2[2][4][4];
#pragma unroll
    for (int i = 0; i < 2; i++)
#pragma unroll
        for (int j = 0; j < 4; j++)
#pragma unroll
            for (int r = 0; r < 4; r++) ac2[i][j][r] = 0.f;

#pragma unroll
    for (int ks = 0; ks < 8; ks++) {
        uint32_t AH[2][4], AL[2][4];
#pragma unroll
        for (int i = 0; i < 2; i++) {
            const float* ap = As + (m0 + 16 * i + q) * 68 + ks * 8 + t4;
            split1(ap[0],          AH[i][0], AL[i][0]);
            split1(ap[8 * 68],     AH[i][1], AL[i][1]);
            split1(ap[4],          AH[i][2], AL[i][2]);
            split1(ap[8 * 68 + 4], AH[i][3], AL[i][3]);
        }
        uint32_t BH[4][2], BL[4][2];
#pragma unroll
        for (int j = 0; j < 4; j++) {
            const float* bp = Wb + (ks * 8 + t4) * 68 + n0 + 8 * j + q;
            split1(bp[0],      BH[j][0], BL[j][0]);
            split1(bp[4 * 68], BH[j][1], BL[j][1]);
        }
#pragma unroll
        for (int i = 0; i < 2; i++)
#pragma unroll
            for (int j = 0; j < 4; j++) {
                mma8(ac2[i][j], AH[i], BH[j]);
                mma8(ac2[i][j], AL[i], BH[j]);
                mma8(ac2[i][j], AH[i], BL[j]);
            }
    }

    // z = relu(D2 + b2) -> stage (zero invalid rows)
    __syncthreads();
#pragma unroll
    for (int i = 0; i < 2; i++)
#pragma unroll
        for (int j = 0; j < 4; j++) {
            int c = n0 + 8 * j + 2 * t4;
            int r0 = m0 + 16 * i + q;
            float2 z0 = make_float2(fmaxf(ac2[i][j][0] + b2s[c], 0.f),
                                    fmaxf(ac2[i][j][1] + b2s[c + 1], 0.f));
            float2 z1 = make_float2(fmaxf(ac2[i][j][2] + b2s[c], 0.f),
                                    fmaxf(ac2[i][j][3] + b2s[c + 1], 0.f));
            if (row0 + r0 >= N_NODES) z0 = make_float2(0.f, 0.f);
            if (row0 + r0 + 8 >= N_NODES) z1 = make_float2(0.f, 0.f);
            *(float2*)(As + r0 * 68 + c) = z0;
            *(float2*)(As + (r0 + 8) * 68 + c) = z1;
        }
    __syncthreads();

    // coalesced STG + BN partials
    float cs0 = 0.f, cs1 = 0.f, cs2 = 0.f, cs3 = 0.f;
    float cq0 = 0.f, cq1 = 0.f, cq2 = 0.f, cq3 = 0.f;
    const int mc4 = tid & 15;
#pragma unroll
    for (int i = 0; i < 8; i++) {
        int f = tid + i * 256;
        int r = f >> 4;
        float4 v = *(const float4*)(As + r * 68 + mc4 * 4);
        cs0 += v.x; cs1 += v.y; cs2 += v.z; cs3 += v.w;
        cq0 += v.x * v.x; cq1 += v.y * v.y; cq2 += v.z * v.z; cq3 += v.w * v.w;
        if (row0 + r < N_NODES)
            *(float4*)(out + (size_t)(row0 + r) * 64 + mc4 * 4) = v;
    }
    atomicAdd(&ssum[mc4 * 4 + 0], cs0);
    atomicAdd(&ssum[mc4 * 4 + 1], cs1);
    atomicAdd(&ssum[mc4 * 4 + 2], cs2);
    atomicAdd(&ssum[mc4 * 4 + 3], cs3);
    atomicAdd(&ssq[mc4 * 4 + 0], cq0);
    atomicAdd(&ssq[mc4 * 4 + 1], cq1);
    atomicAdd(&ssq[mc4 * 4 + 2], cq2);
    atomicAdd(&ssq[mc4 * 4 + 3], cq3);
    __syncthreads();
    if (tid < 64) {
        atomicAdd(bnacc + tid, (double)ssum[tid]);
        atomicAdd(bnacc + 64 + tid, (double)ssq[tid]);
    }
}

// ---------------- pool: g[batch[n]] += BN(z[n]) ------------------------------
__global__ void pool_kernel(const void* __restrict__ batch,
                            const float* __restrict__ zin,
                            const double* __restrict__ acc,
                            const float* __restrict__ gamma,
                            const float* __restrict__ beta)
{
    __shared__ float s_s[64], s_b[64];
    const int tid = threadIdx.x, lane = tid & 31, w = tid >> 5;
    if (tid < 64) {
        double sum = acc[tid], sq = acc[64 + tid];
        float mean = (float)(sum / (double)N_NODES);
        float var = (float)(sq / (double)N_NODES) - mean * mean;
        float sc = gamma[tid] * rsqrtf(var + 1e-5f);
        s_s[tid] = sc;
        s_b[tid] = beta[tid] - mean * sc;
    }
    __syncthreads();
    int node = blockIdx.x * 8 + w;
    if (node >= N_NODES) return;
    const int c0 = lane * 2;
    int b = load_idx(batch, node);
    float2 v = *(const float2*)(zin + (size_t)node * 64 + c0);
    float vx = v.x * s_s[c0] + s_b[c0];
    float vy = v.y * s_s[c0 + 1] + s_b[c0 + 1];
    float* addr = d_g + (size_t)b * 64 + c0;
    asm volatile("red.global.add.v2.f32 [%0], {%1, %2};"
                 :: "l"(addr), "f"(vx), "f"(vy) : "memory");
}

// ---------------- head -------------------------------------------------------
__global__ void head_kernel(const float* __restrict__ W1, const float* __restrict__ b1,
                            const float* __restrict__ W2, const float* __restrict__ b2,
                            float* __restrict__ out)
{
    __shared__ float W1s[64 * 64];
    __shared__ float W2s[64 * 16];
    __shared__ float b1s[64];
    __shared__ float b2s[16];
    int tid = threadIdx.x;
#pragma unroll
    for (int i = 0; i < 16; i++) W1s[tid + i * 256] = W1[tid + i * 256];
#pragma unroll
    for (int i = 0; i < 4; i++) W2s[tid + i * 256] = W2[tid + i * 256];
    if (tid < 64) b1s[tid] = b1[tid];
    if (tid < 16) b2s[tid] = b2[tid];
    __syncthreads();

    int row = blockIdx.x * 256 + tid;
    float gr[64];
#pragma unroll
    for (int k = 0; k < 64; k++) gr[k] = d_g[(size_t)row * 64 + k];
    float oacc[16];
#pragma unroll
    for (int o = 0; o < 16; o++) oacc[o] = b2s[o];

    for (int j = 0; j < 64; j++) {
        float t = b1s[j];
#pragma unroll
        for (int k = 0; k < 64; k++) t += gr[k] * W1s[k * 64 + j];
        t = fmaxf(t, 0.f);
#pragma unroll
        for (int o = 0; o < 16; o++) oacc[o] += t * W2s[j * 16 + o];
    }
#pragma unroll
    for (int o = 0; o < 16; o++) out[(size_t)row * 16 + o] = oacc[o];
}

// =============================================================================
extern "C" void kernel_launch(void* const* d_in, const int* in_sizes, int n_in,
                              void* d_out, int out_size)
{
    const float* x       = (const float*)d_in[0];
    const void*  ei      = d_in[1];
    const void*  batch   = d_in[2];
    const float* enc_W   = (const float*)d_in[3];
    const float* enc_b   = (const float*)d_in[4];
    const float* conv_W1 = (const float*)d_in[5];
    const float* conv_b1 = (const float*)d_in[6];
    const float* conv_W2 = (const float*)d_in[7];
    const float* conv_b2 = (const float*)d_in[8];
    const float* bn_g    = (const float*)d_in[9];
    const float* bn_b    = (const float*)d_in[10];
    const float* fc1_W   = (const float*)d_in[11];
    const float* fc1_b   = (const float*)d_in[12];
    const float* fc2_W   = (const float*)d_in[13];
    const float* fc2_b   = (const float*)d_in[14];
    float* out = (float*)d_out;

    float *z0_p, *z1_p;
    double* acc_p;
    cudaGetSymbolAddress((void**)&z0_p, d_z0);
    cudaGetSymbolAddress((void**)&z1_p, d_z1);
    cudaGetSymbolAddress((void**)&acc_p, d_bnacc);

    cudaFuncSetAttribute(enc_mma,
                         cudaFuncAttributeMaxDynamicSharedMemorySize, SMEM_MMA);
    cudaFuncSetAttribute(gin_mma<false>,
                         cudaFuncAttributeMaxDynamicSharedMemorySize, SMEM_MMA);
    cudaFuncSetAttribute(gin_mma<true>,
                         cudaFuncAttributeMaxDynamicSharedMemorySize, SMEM_MMA);

    const int EB = (N_EDGES + 255) / 256;          // 3125
    const int WB = (N_NODES + 7) / 8;              // 6250
    const int TB = (N_NODES + 127) / 128;          // 391

    zero_detect_kernel<<<(N_NODES + 255) / 256, 256>>>((const unsigned int*)ei);

    count_kernel<<<EB, 256>>>(ei);
    scan1_kernel<<<N_CHUNKS, SCAN_CHUNK>>>();
    scan23_kernel<<<N_CHUNKS, SCAN_CHUNK>>>();
    fill_kernel<<<EB, 256>>>(ei);

    // encoder: z0 = x @ enc_W + enc_b
    enc_mma<<<TB, 256, SMEM_MMA>>>(x, enc_W, enc_b, z0_p);

    // ping-pong: layer l reads buf[l&1], writes buf[1-(l&1)]
    float* bufs[2] = {z0_p, z1_p};
    for (int l = 0; l < N_LAYERS; l++) {
        float* zin = bufs[l & 1];
        float* zout = bufs[1 - (l & 1)];
        if (l == 0)
            gin_mma<false><<<TB, 256, SMEM_MMA>>>(
                zin, conv_W1, conv_b1, conv_W2, conv_b2, zout,
                nullptr, nullptr, nullptr, acc_p);
        else
            gin_mma<true><<<TB, 256, SMEM_MMA>>>(
                zin, conv_W1 + l * 64 * 64, conv_b1 + l * 64,
                conv_W2 + l * 64 * 64, conv_b2 + l * 64, zout,
                acc_p + (l - 1) * 128, bn_g + (l - 1) * 64, bn_b + (l - 1) * 64,
                acc_p + l * 128);
    }

    // after 5 layers output is in bufs[5 & 1] = bufs[1]
    pool_kernel<<<WB, 256>>>(batch, bufs[N_LAYERS & 1],
                             acc_p + 4 * 128, bn_g + 4 * 64, bn_b + 4 * 64);
    head_kernel<<<2, 256>>>(fc1_W, fc1_b, fc2_W, fc2_b, out);
}

// round 12
// speedup vs baseline: 1.0688x; 1.0688x over previous
#include <cuda_runtime.h>
#include <cstdint>

#define N_NODES 50000
#define N_EDGES 800000
#define NODE_DIM 128
#define IN_CH 64
#define OUT_CH 16
#define N_GRAPHS 512
#define N_LAYERS 5

#define SCAN_CHUNK 256
#define N_CHUNKS ((N_NODES + SCAN_CHUNK - 1) / SCAN_CHUNK)   // 196

// ---------------- scratch (device globals; 16B-aligned) ----------------------
__device__ __align__(16) float d_h[N_NODES * IN_CH];    // gathered features
__device__ __align__(16) float d_z[N_NODES * IN_CH];    // MLP output
__device__ __align__(16) double d_bnacc[N_LAYERS * 2 * IN_CH];
__device__ __align__(16) float d_g[N_GRAPHS * IN_CH];
__device__ int d_deg[N_NODES];
__device__ int d_rowptr[N_NODES + 1];
__device__ int d_cursor[N_NODES];
__device__ int d_csrsrc[N_EDGES];
__device__ int d_blocksum[N_CHUNKS];
__device__ int d_idx64;

__device__ __forceinline__ int load_idx(const void* p, long long i) {
    if (d_idx64) return (int)((const long long*)p)[i];
    return ((const int*)p)[i];
}

// ---------------- zero init + dtype sniff (merged) ---------------------------
__global__ void zero_detect_kernel(const unsigned int* __restrict__ ei_words) {
    int i = blockIdx.x * blockDim.x + threadIdx.x;
    if (blockIdx.x == 0) {
        __shared__ int any_nonzero;
        if (threadIdx.x == 0) any_nonzero = 0;
        __syncthreads();
        unsigned w = ei_words[threadIdx.x * 2 + 1];
        if (w != 0u) atomicOr(&any_nonzero, 1);
        __syncthreads();
        if (threadIdx.x == 0) d_idx64 = (any_nonzero == 0) ? 1 : 0;
    }
    if (i < N_NODES) d_deg[i] = 0;
    if (i < N_GRAPHS * IN_CH) d_g[i] = 0.0f;
    if (i < N_LAYERS * 2 * IN_CH) d_bnacc[i] = 0.0;
}

// ---------------- CSR build --------------------------------------------------
__global__ void count_kernel(const void* __restrict__ ei) {
    int e = blockIdx.x * blockDim.x + threadIdx.x;
    if (e >= N_EDGES) return;
    int dst = load_idx(ei, (long long)N_EDGES + e);
    atomicAdd(&d_deg[dst], 1);
}

__global__ void scan1_kernel() {
    __shared__ int wsum[8];
    const int t = threadIdx.x, lane = t & 31, w = t >> 5;
    int i = blockIdx.x * SCAN_CHUNK + t;
    int v = (i < N_NODES) ? d_deg[i] : 0;
    int x = v;
#pragma unroll
    for (int d = 1; d < 32; d <<= 1) x += __shfl_xor_sync(0xFFFFFFFFu, x, d);
    if (lane == 0) wsum[w] = x;
    __syncthreads();
    if (t == 0) {
        int s = 0;
#pragma unroll
        for (int j = 0; j < 8; j++) s += wsum[j];
        d_blocksum[blockIdx.x] = s;
    }
}

// merged pass 2+3: every block scans the 196 partials, then its own chunk
__global__ void scan23_kernel() {
    __shared__ int sh[N_CHUNKS];
    __shared__ int wsum[8];
    const int t = threadIdx.x, lane = t & 31, w = t >> 5;
    if (t < N_CHUNKS) sh[t] = d_blocksum[t];
    __syncthreads();
    for (int d = 1; d < N_CHUNKS; d <<= 1) {
        int x = 0;
        if (t < N_CHUNKS && t >= d) x = sh[t - d];
        __syncthreads();
        if (t < N_CHUNKS && t >= d) sh[t] += x;
        __syncthreads();
    }
    const int chunk_off = (blockIdx.x > 0) ? sh[blockIdx.x - 1] : 0;
    if (blockIdx.x == 0 && t == 0) d_rowptr[N_NODES] = N_EDGES;

    int i = blockIdx.x * SCAN_CHUNK + t;
    int v = (i < N_NODES) ? d_deg[i] : 0;
    int x = v;
#pragma unroll
    for (int d = 1; d < 32; d <<= 1) {
        int y = __shfl_up_sync(0xFFFFFFFFu, x, d);
        if (lane >= d) x += y;
    }
    if (lane == 31) wsum[w] = x;
    __syncthreads();
    if (w == 0 && lane < 8) {
        int y = wsum[lane];
#pragma unroll
        for (int d = 1; d < 8; d <<= 1) {
            int z = __shfl_up_sync(0xFFu, y, d);
            if (lane >= d) y += z;
        }
        wsum[lane] = y;
    }
    __syncthreads();
    int excl = chunk_off + (w > 0 ? wsum[w - 1] : 0) + x - v;
    if (i < N_NODES) { d_rowptr[i] = excl; d_cursor[i] = excl; }
}

__global__ void fill_kernel(const void* __restrict__ ei) {
    int e = blockIdx.x * blockDim.x + threadIdx.x;
    if (e >= N_EDGES) return;
    int src = load_idx(ei, e);
    int dst = load_idx(ei, (long long)N_EDGES + e);
    int pos = atomicAdd(&d_cursor[dst], 1);
    d_csrsrc[pos] = src;
}

// ---------------- aggregation (standalone, high occupancy, ILP-4) ------------
// h[n] = BN(z)[n] + sum_{src->n} BN(z)[src]; warp per node, lane = 2 channels.
template<bool BN>
__global__ void agg_kernel(const float* __restrict__ zin, float* __restrict__ hout,
                           const double* __restrict__ acc,
                           const float* __restrict__ gamma,
                           const float* __restrict__ beta)
{
    __shared__ float s_s[64], s_b[64];
    const int tid = threadIdx.x, lane = tid & 31, w = tid >> 5;
    if (BN) {
        if (tid < 64) {
            double sum = acc[tid], sq = acc[64 + tid];
            float mean = (float)(sum / (double)N_NODES);
            float var = (float)(sq / (double)N_NODES) - mean * mean;
            float sc = gamma[tid] * rsqrtf(var + 1e-5f);
            s_s[tid] = sc;
            s_b[tid] = beta[tid] - mean * sc;
        }
        __syncthreads();
    }
    int node = blockIdx.x * 8 + w;
    if (node >= N_NODES) return;
    const int c0 = lane * 2;
    const float sx = BN ? s_s[c0] : 1.f, sy = BN ? s_s[c0 + 1] : 1.f;
    const float bx = BN ? s_b[c0] : 0.f, by = BN ? s_b[c0 + 1] : 0.f;

    float2 v = *(const float2*)(zin + (size_t)node * 64 + c0);
    float ax0 = v.x * sx + bx, ay0 = v.y * sy + by;
    float ax1 = 0.f, ay1 = 0.f;

    int j = d_rowptr[node];
    const int r1 = d_rowptr[node + 1];
    for (; j + 3 < r1; j += 4) {
        int i0 = d_csrsrc[j + 0];
        int i1 = d_csrsrc[j + 1];
        int i2 = d_csrsrc[j + 2];
        int i3 = d_csrsrc[j + 3];
        float2 v0 = *(const float2*)(zin + (size_t)i0 * 64 + c0);
        float2 v1 = *(const float2*)(zin + (size_t)i1 * 64 + c0);
        float2 v2 = *(const float2*)(zin + (size_t)i2 * 64 + c0);
        float2 v3 = *(const float2*)(zin + (size_t)i3 * 64 + c0);
        ax0 += v0.x * sx + bx; ay0 += v0.y * sy + by;
        ax1 += v1.x * sx + bx; ay1 += v1.y * sy + by;
        ax0 += v2.x * sx + bx; ay0 += v2.y * sy + by;
        ax1 += v3.x * sx + bx; ay1 += v3.y * sy + by;
    }
    if (j + 1 < r1) {
        int i0 = d_csrsrc[j], i1 = d_csrsrc[j + 1];
        float2 v0 = *(const float2*)(zin + (size_t)i0 * 64 + c0);
        float2 v1 = *(const float2*)(zin + (size_t)i1 * 64 + c0);
        ax0 += v0.x * sx + bx; ay0 += v0.y * sy + by;
        ax1 += v1.x * sx + bx; ay1 += v1.y * sy + by;
        j += 2;
    }
    if (j < r1) {
        int i0 = d_csrsrc[j];
        float2 v0 = *(const float2*)(zin + (size_t)i0 * 64 + c0);
        ax0 += v0.x * sx + bx; ay0 += v0.y * sy + by;
    }
    *(float2*)(hout + (size_t)node * 64 + c0) = make_float2(ax0 + ax1, ay0 + ay1);
}

// =============================================================================
// mma.sync tf32 split-precision GEMM machinery
// =============================================================================
__device__ __forceinline__ void mma8(float* d, const uint32_t* a, const uint32_t* b) {
    asm volatile(
        "mma.sync.aligned.m16n8k8.row.col.f32.tf32.tf32.f32 "
        "{%0,%1,%2,%3}, {%4,%5,%6,%7}, {%8,%9}, {%0,%1,%2,%3};"
        : "+f"(d[0]), "+f"(d[1]), "+f"(d[2]), "+f"(d[3])
        : "r"(a[0]), "r"(a[1]), "r"(a[2]), "r"(a[3]), "r"(b[0]), "r"(b[1]));
}
__device__ __forceinline__ void split1(float x, uint32_t& hi, uint32_t& lo) {
    uint32_t h = __float_as_uint(x) & 0xFFFFE000u;
    hi = h;
    lo = __float_as_uint(x - __uint_as_float(h));
}

// smem (floats): As 128x68, Ws 64x68, Wb 64x68, b1s/b2s/ssum/ssq 64 each
#define F_AS   0
#define F_WS   8704
#define F_WB   13056
#define F_B1   17408
#define F_B2   17472
#define F_SS   17536
#define F_SQ   17600
#define SMEM_MMA (17664 * 4)

template<int KC, bool FUSED>
__global__ void __launch_bounds__(256)
mlp_mma(const float* __restrict__ A, const float* __restrict__ W1g,
        const float* __restrict__ b1, const float* __restrict__ W2g,
        const float* __restrict__ b2, float* __restrict__ out,
        double* __restrict__ bnacc)
{
    extern __shared__ __align__(16) float sm[];
    float* As  = sm + F_AS;
    float* Ws  = sm + F_WS;
    float* Wb  = sm + F_WB;
    float* b1s = sm + F_B1;
    float* b2s = sm + F_B2;
    float* ssum = sm + F_SS;
    float* ssq  = sm + F_SQ;

    const int tid = threadIdx.x, lane = tid & 31, wid = tid >> 5;
    const int q = lane >> 2, t4 = lane & 3;
    const int m0 = (wid & 3) * 32, n0 = (wid >> 2) * 32;
    const int row0 = blockIdx.x * 128;
    const int KT = KC * 64;

    if (tid < 64) {
        b1s[tid] = b1[tid];
        if (FUSED) { b2s[tid] = b2[tid]; ssum[tid] = 0.f; ssq[tid] = 0.f; }
    }
    if (FUSED) {
#pragma unroll
        for (int i = 0; i < 4; i++) {
            int f = tid + i * 256;
            int k = f >> 4, c4 = f & 15;
            *(float4*)(Wb + k * 68 + c4 * 4) = *(const float4*)(W2g + k * 64 + c4 * 4);
        }
    }

    float acc[2][4][4];
#pragma unroll
    for (int i = 0; i < 2; i++)
#pragma unroll
        for (int j = 0; j < 4; j++)
#pragma unroll
            for (int r = 0; r < 4; r++) acc[i][j][r] = 0.f;

    for (int kc = 0; kc < KC; kc++) {
        if (kc) __syncthreads();
#pragma unroll
        for (int i = 0; i < 8; i++) {
            int f = tid + i * 256;
            int r = f >> 4, c4 = f & 15;
            int gr = row0 + r;
            float4 v = make_float4(0.f, 0.f, 0.f, 0.f);
            if (gr < N_NODES)
                v = *(const float4*)(A + (size_t)gr * KT + kc * 64 + c4 * 4);
            *(float4*)(As + r * 68 + c4 * 4) = v;
        }
#pragma unroll
        for (int i = 0; i < 4; i++) {
            int f = tid + i * 256;
            int k = f >> 4, c4 = f & 15;
            *(float4*)(Ws + k * 68 + c4 * 4) =
                *(const float4*)(W1g + (size_t)(kc * 64 + k) * 64 + c4 * 4);
        }
        __syncthreads();

#pragma unroll
        for (int ks = 0; ks < 8; ks++) {
            uint32_t AH[2][4], AL[2][4];
#pragma unroll
            for (int i = 0; i < 2; i++) {
                const float* ap = As + (m0 + 16 * i + q) * 68 + ks * 8 + t4;
                split1(ap[0],          AH[i][0], AL[i][0]);
                split1(ap[8 * 68],     AH[i][1], AL[i][1]);
                split1(ap[4],          AH[i][2], AL[i][2]);
                split1(ap[8 * 68 + 4], AH[i][3], AL[i][3]);
            }
            uint32_t BH[4][2], BL[4][2];
#pragma unroll
            for (int j = 0; j < 4; j++) {
                const float* bp = Ws + (ks * 8 + t4) * 68 + n0 + 8 * j + q;
                split1(bp[0],      BH[j][0], BL[j][0]);
                split1(bp[4 * 68], BH[j][1], BL[j][1]);
            }
#pragma unroll
            for (int i = 0; i < 2; i++)
#pragma unroll
                for (int j = 0; j < 4; j++) {
                    mma8(acc[i][j], AH[i], BH[j]);
                    mma8(acc[i][j], AL[i], BH[j]);
                    mma8(acc[i][j], AH[i], BL[j]);
                }
        }
    }

    if (!FUSED) {
        __syncthreads();
#pragma unroll
        for (int i = 0; i < 2; i++)
#pragma unroll
            for (int j = 0; j < 4; j++) {
                int c = n0 + 8 * j + 2 * t4;
                int r0 = m0 + 16 * i + q;
                *(float2*)(As + r0 * 68 + c) =
                    make_float2(acc[i][j][0] + b1s[c], acc[i][j][1] + b1s[c + 1]);
                *(float2*)(As + (r0 + 8) * 68 + c) =
                    make_float2(acc[i][j][2] + b1s[c], acc[i][j][3] + b1s[c + 1]);
            }
        __syncthreads();
#pragma unroll
        for (int i = 0; i < 8; i++) {
            int f = tid + i * 256;
            int r = f >> 4, c4 = f & 15;
            if (row0 + r < N_NODES)
                *(float4*)(out + (size_t)(row0 + r) * 64 + c4 * 4) =
                    *(const float4*)(As + r * 68 + c4 * 4);
        }
        return;
    }

    // T = relu(D + b1) -> As
    __syncthreads();
#pragma unroll
    for (int i = 0; i < 2; i++)
#pragma unroll
        for (int j = 0; j < 4; j++) {
            int c = n0 + 8 * j + 2 * t4;
            int r0 = m0 + 16 * i + q;
            *(float2*)(As + r0 * 68 + c) =
                make_float2(fmaxf(acc[i][j][0] + b1s[c], 0.f),
                            fmaxf(acc[i][j][1] + b1s[c + 1], 0.f));
            *(float2*)(As + (r0 + 8) * 68 + c) =
                make_float2(fmaxf(acc[i][j][2] + b1s[c], 0.f),
                            fmaxf(acc[i][j][3] + b1s[c + 1], 0.f));
        }
    __syncthreads();

    // stage 2: D2 = T @ W2
    float ac2[2][4][4];
#pragma unroll
    for (int i = 0; i < 2; i++)
#pragma unroll
        for (int j = 0; j < 4; j++)
#pragma unroll
            for (int r = 0; r < 4; r++) ac2[i][j][r] = 0.f;

#pragma unroll
    for (int ks = 0; ks < 8; ks++) {
        uint32_t AH[2][4], AL[2][4];
#pragma unroll
        for (int i = 0; i < 2; i++) {
            const float* ap = As + (m0 + 16 * i + q) * 68 + ks * 8 + t4;
            split1(ap[0],          AH[i][0], AL[i][0]);
            split1(ap[8 * 68],     AH[i][1], AL[i][1]);
            split1(ap[4],          AH[i][2], AL[i][2]);
            split1(ap[8 * 68 + 4], AH[i][3], AL[i][3]);
        }
        uint32_t BH[4][2], BL[4][2];
#pragma unroll
        for (int j = 0; j < 4; j++) {
            const float* bp = Wb + (ks * 8 + t4) * 68 + n0 + 8 * j + q;
            split1(bp[0],      BH[j][0], BL[j][0]);
            split1(bp[4 * 68], BH[j][1], BL[j][1]);
        }
#pragma unroll
        for (int i = 0; i < 2; i++)
#pragma unroll
            for (int j = 0; j < 4; j++) {
                mma8(ac2[i][j], AH[i], BH[j]);
                mma8(ac2[i][j], AL[i], BH[j]);
                mma8(ac2[i][j], AH[i], BL[j]);
            }
    }

    // z = relu(D2 + b2) -> stage (zero invalid rows)
    __syncthreads();
#pragma unroll
    for (int i = 0; i < 2; i++)
#pragma unroll
        for (int j = 0; j < 4; j++) {
            int c = n0 + 8 * j + 2 * t4;
            int r0 = m0 + 16 * i + q;
            float2 z0 = make_float2(fmaxf(ac2[i][j][0] + b2s[c], 0.f),
                                    fmaxf(ac2[i][j][1] + b2s[c + 1], 0.f));
            float2 z1 = make_float2(fmaxf(ac2[i][j][2] + b2s[c], 0.f),
                                    fmaxf(ac2[i][j][3] + b2s[c + 1], 0.f));
            if (row0 + r0 >= N_NODES) z0 = make_float2(0.f, 0.f);
            if (row0 + r0 + 8 >= N_NODES) z1 = make_float2(0.f, 0.f);
            *(float2*)(As + r0 * 68 + c) = z0;
            *(float2*)(As + (r0 + 8) * 68 + c) = z1;
        }
    __syncthreads();

    // coalesced STG + BN partials
    float cs0 = 0.f, cs1 = 0.f, cs2 = 0.f, cs3 = 0.f;
    float cq0 = 0.f, cq1 = 0.f, cq2 = 0.f, cq3 = 0.f;
    const int mc4 = tid & 15;
#pragma unroll
    for (int i = 0; i < 8; i++) {
        int f = tid + i * 256;
        int r = f >> 4;
        float4 v = *(const float4*)(As + r * 68 + mc4 * 4);
        cs0 += v.x; cs1 += v.y; cs2 += v.z; cs3 += v.w;
        cq0 += v.x * v.x; cq1 += v.y * v.y; cq2 += v.z * v.z; cq3 += v.w * v.w;
        if (row0 + r < N_NODES)
            *(float4*)(out + (size_t)(row0 + r) * 64 + mc4 * 4) = v;
    }
    atomicAdd(&ssum[mc4 * 4 + 0], cs0);
    atomicAdd(&ssum[mc4 * 4 + 1], cs1);
    atomicAdd(&ssum[mc4 * 4 + 2], cs2);
    atomicAdd(&ssum[mc4 * 4 + 3], cs3);
    atomicAdd(&ssq[mc4 * 4 + 0], cq0);
    atomicAdd(&ssq[mc4 * 4 + 1], cq1);
    atomicAdd(&ssq[mc4 * 4 + 2], cq2);
    atomicAdd(&ssq[mc4 * 4 + 3], cq3);
    __syncthreads();
    if (tid < 64) {
        atomicAdd(bnacc + tid, (double)ssum[tid]);
        atomicAdd(bnacc + 64 + tid, (double)ssq[tid]);
    }
}

// ---------------- pool: g[batch[n]] += BN(z[n]) ------------------------------
__global__ void pool_kernel(const void* __restrict__ batch,
                            const float* __restrict__ zin,
                            const double* __restrict__ acc,
                            const float* __restrict__ gamma,
                            const float* __restrict__ beta)
{
    __shared__ float s_s[64], s_b[64];
    const int tid = threadIdx.x, lane = tid & 31, w = tid >> 5;
    if (tid < 64) {
        double sum = acc[tid], sq = acc[64 + tid];
        float mean = (float)(sum / (double)N_NODES);
        float var = (float)(sq / (double)N_NODES) - mean * mean;
        float sc = gamma[tid] * rsqrtf(var + 1e-5f);
        s_s[tid] = sc;
        s_b[tid] = beta[tid] - mean * sc;
    }
    __syncthreads();
    int node = blockIdx.x * 8 + w;
    if (node >= N_NODES) return;
    const int c0 = lane * 2;
    int b = load_idx(batch, node);
    float2 v = *(const float2*)(zin + (size_t)node * 64 + c0);
    float vx = v.x * s_s[c0] + s_b[c0];
    float vy = v.y * s_s[c0 + 1] + s_b[c0 + 1];
    float* addr = d_g + (size_t)b * 64 + c0;
    asm volatile("red.global.add.v2.f32 [%0], {%1, %2};"
                 :: "l"(addr), "f"(vx), "f"(vy) : "memory");
}

// ---------------- head -------------------------------------------------------
__global__ void head_kernel(const float* __restrict__ W1, const float* __restrict__ b1,
                            const float* __restrict__ W2, const float* __restrict__ b2,
                            float* __restrict__ out)
{
    __shared__ float W1s[64 * 64];
    __shared__ float W2s[64 * 16];
    __shared__ float b1s[64];
    __shared__ float b2s[16];
    int tid = threadIdx.x;
#pragma unroll
    for (int i = 0; i < 16; i++) W1s[tid + i * 256] = W1[tid + i * 256];
#pragma unroll
    for (int i = 0; i < 4; i++) W2s[tid + i * 256] = W2[tid + i * 256];
    if (tid < 64) b1s[tid] = b1[tid];
    if (tid < 16) b2s[tid] = b2[tid];
    __syncthreads();

    int row = blockIdx.x * 256 + tid;
    float gr[64];
#pragma unroll
    for (int k = 0; k < 64; k++) gr[k] = d_g[(size_t)row * 64 + k];
    float oacc[16];
#pragma unroll
    for (int o = 0; o < 16; o++) oacc[o] = b2s[o];

    for (int j = 0; j < 64; j++) {
        float t = b1s[j];
#pragma unroll
        for (int k = 0; k < 64; k++) t += gr[k] * W1s[k * 64 + j];
        t = fmaxf(t, 0.f);
#pragma unroll
        for (int o = 0; o < 16; o++) oacc[o] += t * W2s[j * 16 + o];
    }
#pragma unroll
    for (int o = 0; o < 16; o++) out[(size_t)row * 16 + o] = oacc[o];
}

// =============================================================================
extern "C" void kernel_launch(void* const* d_in, const int* in_sizes, int n_in,
                              void* d_out, int out_size)
{
    const float* x       = (const float*)d_in[0];
    const void*  ei      = d_in[1];
    const void*  batch   = d_in[2];
    const float* enc_W   = (const float*)d_in[3];
    const float* enc_b   = (const float*)d_in[4];
    const float* conv_W1 = (const float*)d_in[5];
    const float* conv_b1 = (const float*)d_in[6];
    const float* conv_W2 = (const float*)d_in[7];
    const float* conv_b2 = (const float*)d_in[8];
    const float* bn_g    = (const float*)d_in[9];
    const float* bn_b    = (const float*)d_in[10];
    const float* fc1_W   = (const float*)d_in[11];
    const float* fc1_b   = (const float*)d_in[12];
    const float* fc2_W   = (const float*)d_in[13];
    const float* fc2_b   = (const float*)d_in[14];
    float* out = (float*)d_out;

    float *h_p, *z_p;
    double* acc_p;
    cudaGetSymbolAddress((void**)&h_p, d_h);
    cudaGetSymbolAddress((void**)&z_p, d_z);
    cudaGetSymbolAddress((void**)&acc_p, d_bnacc);

    cudaFuncSetAttribute(mlp_mma<2, false>,
                         cudaFuncAttributeMaxDynamicSharedMemorySize, SMEM_MMA);
    cudaFuncSetAttribute(mlp_mma<1, true>,
                         cudaFuncAttributeMaxDynamicSharedMemorySize, SMEM_MMA);

    const int EB = (N_EDGES + 255) / 256;          // 3125
    const int WB = (N_NODES + 7) / 8;              // 6250
    const int TB = (N_NODES + 127) / 128;          // 391

    zero_detect_kernel<<<(N_NODES + 255) / 256, 256>>>((const unsigned int*)ei);

    count_kernel<<<EB, 256>>>(ei);
    scan1_kernel<<<N_CHUNKS, SCAN_CHUNK>>>();
    scan23_kernel<<<N_CHUNKS, SCAN_CHUNK>>>();
    fill_kernel<<<EB, 256>>>(ei);

    // encoder: z = x @ enc_W + enc_b
    mlp_mma<2, false><<<TB, 256, SMEM_MMA>>>(x, enc_W, enc_b, nullptr, nullptr,
                                             z_p, nullptr);

    for (int l = 0; l < N_LAYERS; l++) {
        if (l == 0)
            agg_kernel<false><<<WB, 256>>>(z_p, h_p, nullptr, nullptr, nullptr);
        else
            agg_kernel<true><<<WB, 256>>>(z_p, h_p, acc_p + (l - 1) * 128,
                                          bn_g + (l - 1) * 64, bn_b + (l - 1) * 64);
        mlp_mma<1, true><<<TB, 256, SMEM_MMA>>>(h_p, conv_W1 + l * 64 * 64,
                                                conv_b1 + l * 64,
                                                conv_W2 + l * 64 * 64,
                                                conv_b2 + l * 64,
                                                z_p, acc_p + l * 128);
    }

    pool_kernel<<<WB, 256>>>(batch, z_p, acc_p + 4 * 128, bn_g + 4 * 64, bn_b + 4 * 64);
    head_kernel<<<2, 256>>>(fc1_W, fc1_b, fc2_W, fc2_b, out);
}

// round 17
// speedup vs baseline: 1.0948x; 1.0243x over previous
#include <cuda_runtime.h>
#include <cuda_fp16.h>
#include <cstdint>
#include <cstring>

#define N_NODES 50000
#define N_EDGES 800000
#define NODE_DIM 128
#define IN_CH 64
#define OUT_CH 16
#define N_GRAPHS 512
#define N_LAYERS 5

#define SCAN_CHUNK 256
#define N_CHUNKS ((N_NODES + SCAN_CHUNK - 1) / SCAN_CHUNK)   // 196

// ---------------- scratch (device globals; 16B-aligned) ----------------------
__device__ __align__(16) float d_h[N_NODES * IN_CH];    // gathered features
__device__ __align__(16) float d_z[N_NODES * IN_CH];    // MLP output
__device__ __align__(16) double d_bnacc[N_LAYERS * 2 * IN_CH];
__device__ __align__(16) float d_g[N_GRAPHS * IN_CH];
__device__ int d_deg[N_NODES];
__device__ int d_rowptr[N_NODES + 1];
__device__ int d_cursor[N_NODES];
__device__ int d_csrsrc[N_EDGES];
__device__ int d_blocksum[N_CHUNKS];
__device__ int d_idx64;

__device__ __forceinline__ int load_idx(const void* p, long long i) {
    if (d_idx64) return (int)((const long long*)p)[i];
    return ((const int*)p)[i];
}

// ---------------- zero init + dtype sniff (merged) ---------------------------
__global__ void zero_detect_kernel(const unsigned int* __restrict__ ei_words) {
    int i = blockIdx.x * blockDim.x + threadIdx.x;
    if (blockIdx.x == 0) {
        __shared__ int any_nonzero;
        if (threadIdx.x == 0) any_nonzero = 0;
        __syncthreads();
        unsigned w = ei_words[threadIdx.x * 2 + 1];
        if (w != 0u) atomicOr(&any_nonzero, 1);
        __syncthreads();
        if (threadIdx.x == 0) d_idx64 = (any_nonzero == 0) ? 1 : 0;
    }
    if (i < N_NODES) d_deg[i] = 0;
    if (i < N_GRAPHS * IN_CH) d_g[i] = 0.0f;
    if (i < N_LAYERS * 2 * IN_CH) d_bnacc[i] = 0.0;
}

// ---------------- CSR build --------------------------------------------------
__global__ void count_kernel(const void* __restrict__ ei) {
    int e = blockIdx.x * blockDim.x + threadIdx.x;
    if (e >= N_EDGES) return;
    int dst = load_idx(ei, (long long)N_EDGES + e);
    atomicAdd(&d_deg[dst], 1);
}

__global__ void scan1_kernel() {
    __shared__ int wsum[8];
    const int t = threadIdx.x, lane = t & 31, w = t >> 5;
    int i = blockIdx.x * SCAN_CHUNK + t;
    int v = (i < N_NODES) ? d_deg[i] : 0;
    int x = v;
#pragma unroll
    for (int d = 1; d < 32; d <<= 1) x += __shfl_xor_sync(0xFFFFFFFFu, x, d);
    if (lane == 0) wsum[w] = x;
    __syncthreads();
    if (t == 0) {
        int s = 0;
#pragma unroll
        for (int j = 0; j < 8; j++) s += wsum[j];
        d_blocksum[blockIdx.x] = s;
    }
}

// merged pass 2+3: every block scans the 196 partials, then its own chunk
__global__ void scan23_kernel() {
    __shared__ int sh[N_CHUNKS];
    __shared__ int wsum[8];
    const int t = threadIdx.x, lane = t & 31, w = t >> 5;
    if (t < N_CHUNKS) sh[t] = d_blocksum[t];
    __syncthreads();
    for (int d = 1; d < N_CHUNKS; d <<= 1) {
        int x = 0;
        if (t < N_CHUNKS && t >= d) x = sh[t - d];
        __syncthreads();
        if (t < N_CHUNKS && t >= d) sh[t] += x;
        __syncthreads();
    }
    const int chunk_off = (blockIdx.x > 0) ? sh[blockIdx.x - 1] : 0;
    if (blockIdx.x == 0 && t == 0) d_rowptr[N_NODES] = N_EDGES;

    int i = blockIdx.x * SCAN_CHUNK + t;
    int v = (i < N_NODES) ? d_deg[i] : 0;
    int x = v;
#pragma unroll
    for (int d = 1; d < 32; d <<= 1) {
        int y = __shfl_up_sync(0xFFFFFFFFu, x, d);
        if (lane >= d) x += y;
    }
    if (lane == 31) wsum[w] = x;
    __syncthreads();
    if (w == 0 && lane < 8) {
        int y = wsum[lane];
#pragma unroll
        for (int d = 1; d < 8; d <<= 1) {
            int z = __shfl_up_sync(0xFFu, y, d);
            if (lane >= d) y += z;
        }
        wsum[lane] = y;
    }
    __syncthreads();
    int excl = chunk_off + (w > 0 ? wsum[w - 1] : 0) + x - v;
    if (i < N_NODES) { d_rowptr[i] = excl; d_cursor[i] = excl; }
}

__global__ void fill_kernel(const void* __restrict__ ei) {
    int e = blockIdx.x * blockDim.x + threadIdx.x;
    if (e >= N_EDGES) return;
    int src = load_idx(ei, e);
    int dst = load_idx(ei, (long long)N_EDGES + e);
    int pos = atomicAdd(&d_cursor[dst], 1);
    d_csrsrc[pos] = src;
}

// ---------------- aggregation (fp32, high occupancy, ILP-4) ------------------
template<bool BN>
__global__ void agg_kernel(const float* __restrict__ zin, float* __restrict__ hout,
                           const double* __restrict__ acc,
                           const float* __restrict__ gamma,
                           const float* __restrict__ beta)
{
    __shared__ float s_s[64], s_b[64];
    const int tid = threadIdx.x, lane = tid & 31, w = tid >> 5;
    if (BN) {
        if (tid < 64) {
            double sum = acc[tid], sq = acc[64 + tid];
            float mean = (float)(sum / (double)N_NODES);
            float var = (float)(sq / (double)N_NODES) - mean * mean;
            float sc = gamma[tid] * rsqrtf(var + 1e-5f);
            s_s[tid] = sc;
            s_b[tid] = beta[tid] - mean * sc;
        }
        __syncthreads();
    }
    int node = blockIdx.x * 8 + w;
    if (node >= N_NODES) return;
    const int c0 = lane * 2;
    const float sx = BN ? s_s[c0] : 1.f, sy = BN ? s_s[c0 + 1] : 1.f;
    const float bx = BN ? s_b[c0] : 0.f, by = BN ? s_b[c0 + 1] : 0.f;

    float2 v = *(const float2*)(zin + (size_t)node * 64 + c0);
    float ax0 = v.x * sx + bx, ay0 = v.y * sy + by;
    float ax1 = 0.f, ay1 = 0.f;

    int j = d_rowptr[node];
    const int r1 = d_rowptr[node + 1];
    for (; j + 3 < r1; j += 4) {
        int i0 = d_csrsrc[j + 0];
        int i1 = d_csrsrc[j + 1];
        int i2 = d_csrsrc[j + 2];
        int i3 = d_csrsrc[j + 3];
        float2 v0 = *(const float2*)(zin + (size_t)i0 * 64 + c0);
        float2 v1 = *(const float2*)(zin + (size_t)i1 * 64 + c0);
        float2 v2 = *(const float2*)(zin + (size_t)i2 * 64 + c0);
        float2 v3 = *(const float2*)(zin + (size_t)i3 * 64 + c0);
        ax0 += v0.x * sx + bx; ay0 += v0.y * sy + by;
        ax1 += v1.x * sx + bx; ay1 += v1.y * sy + by;
        ax0 += v2.x * sx + bx; ay0 += v2.y * sy + by;
        ax1 += v3.x * sx + bx; ay1 += v3.y * sy + by;
    }
    if (j + 1 < r1) {
        int i0 = d_csrsrc[j], i1 = d_csrsrc[j + 1];
        float2 v0 = *(const float2*)(zin + (size_t)i0 * 64 + c0);
        float2 v1 = *(const float2*)(zin + (size_t)i1 * 64 + c0);
        ax0 += v0.x * sx + bx; ay0 += v0.y * sy + by;
        ax1 += v1.x * sx + bx; ay1 += v1.y * sy + by;
        j += 2;
    }
    if (j < r1) {
        int i0 = d_csrsrc[j];
        float2 v0 = *(const float2*)(zin + (size_t)i0 * 64 + c0);
        ax0 += v0.x * sx + bx; ay0 += v0.y * sy + by;
    }
    *(float2*)(hout + (size_t)node * 64 + c0) = make_float2(ax0 + ax1, ay0 + ay1);
}

// =============================================================================
// mma.sync fp16 two-term-split GEMM (m16n8k16, 3-term products, fp32 accum)
// =============================================================================
__device__ __forceinline__ void mma16(float* d, const uint32_t* a, const uint32_t* b) {
    asm volatile(
        "mma.sync.aligned.m16n8k16.row.col.f32.f16.f16.f32 "
        "{%0,%1,%2,%3}, {%4,%5,%6,%7}, {%8,%9}, {%0,%1,%2,%3};"
        : "+f"(d[0]), "+f"(d[1]), "+f"(d[2]), "+f"(d[3])
        : "r"(a[0]), "r"(a[1]), "r"(a[2]), "r"(a[3]), "r"(b[0]), "r"(b[1]));
}
// split fp32 pair -> fp16 hi pair + fp16 lo pair (exact residual)
__device__ __forceinline__ void split_h2(float2 v, uint32_t& hi, uint32_t& lo) {
    __half2 h = __float22half2_rn(v);
    float2 hf = __half22float2(h);
    __half2 l = __float22half2_rn(make_float2(v.x - hf.x, v.y - hf.y));
    memcpy(&hi, &h, 4);
    memcpy(&lo, &l, 4);
}

// smem (floats): As 128x68, Ws 64x68, Wb 64x68, b1s/b2s/ssum/ssq 64 each
#define F_AS   0
#define F_WS   8704
#define F_WB   13056
#define F_B1   17408
#define F_B2   17472
#define F_SS   17536
#define F_SQ   17600
#define SMEM_MMA (17664 * 4)

template<int KC, bool FUSED>
__global__ void __launch_bounds__(256)
mlp_mma(const float* __restrict__ A, const float* __restrict__ W1g,
        const float* __restrict__ b1, const float* __restrict__ W2g,
        const float* __restrict__ b2, float* __restrict__ out,
        double* __restrict__ bnacc)
{
    extern __shared__ __align__(16) float sm[];
    float* As  = sm + F_AS;
    float* Ws  = sm + F_WS;
    float* Wb  = sm + F_WB;
    float* b1s = sm + F_B1;
    float* b2s = sm + F_B2;
    float* ssum = sm + F_SS;
    float* ssq  = sm + F_SQ;

    const int tid = threadIdx.x, lane = tid & 31, wid = tid >> 5;
    const int q = lane >> 2, t4 = lane & 3;
    const int m0 = (wid & 3) * 32, n0 = (wid >> 2) * 32;
    const int row0 = blockIdx.x * 128;
    const int KT = KC * 64;

    if (tid < 64) {
        b1s[tid] = b1[tid];
        if (FUSED) { b2s[tid] = b2[tid]; ssum[tid] = 0.f; ssq[tid] = 0.f; }
    }
    if (FUSED) {
#pragma unroll
        for (int i = 0; i < 4; i++) {
            int f = tid + i * 256;
            int k = f >> 4, c4 = f & 15;
            *(float4*)(Wb + k * 68 + c4 * 4) = *(const float4*)(W2g + k * 64 + c4 * 4);
        }
    }

    float acc[2][4][4];
#pragma unroll
    for (int i = 0; i < 2; i++)
#pragma unroll
        for (int j = 0; j < 4; j++)
#pragma unroll
            for (int r = 0; r < 4; r++) acc[i][j][r] = 0.f;

    for (int kc = 0; kc < KC; kc++) {
        if (kc) __syncthreads();
#pragma unroll
        for (int i = 0; i < 8; i++) {
            int f = tid + i * 256;
            int r = f >> 4, c4 = f & 15;
            int gr = row0 + r;
            float4 v = make_float4(0.f, 0.f, 0.f, 0.f);
            if (gr < N_NODES)
                v = *(const float4*)(A + (size_t)gr * KT + kc * 64 + c4 * 4);
            *(float4*)(As + r * 68 + c4 * 4) = v;
        }
#pragma unroll
        for (int i = 0; i < 4; i++) {
            int f = tid + i * 256;
            int k = f >> 4, c4 = f & 15;
            *(float4*)(Ws + k * 68 + c4 * 4) =
                *(const float4*)(W1g + (size_t)(kc * 64 + k) * 64 + c4 * 4);
        }
        __syncthreads();

#pragma unroll
        for (int ks = 0; ks < 4; ks++) {          // K=16 per step
            const int kk = ks * 16;
            uint32_t AH[2][4], AL[2][4];
#pragma unroll
            for (int i = 0; i < 2; i++) {
                const float* ap = As + (m0 + 16 * i + q) * 68 + kk + 2 * t4;
                split_h2(*(const float2*)(ap),              AH[i][0], AL[i][0]);
                split_h2(*(const float2*)(ap + 8 * 68),     AH[i][1], AL[i][1]);
                split_h2(*(const float2*)(ap + 8),          AH[i][2], AL[i][2]);
                split_h2(*(const float2*)(ap + 8 * 68 + 8), AH[i][3], AL[i][3]);
            }
            uint32_t BH[4][2], BL[4][2];
#pragma unroll
            for (int j = 0; j < 4; j++) {
                const float* bp = Ws + (kk + 2 * t4) * 68 + n0 + 8 * j + q;
                split_h2(make_float2(bp[0], bp[68]),           BH[j][0], BL[j][0]);
                split_h2(make_float2(bp[8 * 68], bp[9 * 68]),  BH[j][1], BL[j][1]);
            }
#pragma unroll
            for (int i = 0; i < 2; i++)
#pragma unroll
                for (int j = 0; j < 4; j++) {
                    mma16(acc[i][j], AH[i], BH[j]);
                    mma16(acc[i][j], AL[i], BH[j]);
                    mma16(acc[i][j], AH[i], BL[j]);
                }
        }
    }

    if (!FUSED) {
        __syncthreads();
#pragma unroll
        for (int i = 0; i < 2; i++)
#pragma unroll
            for (int j = 0; j < 4; j++) {
                int c = n0 + 8 * j + 2 * t4;
                int r0 = m0 + 16 * i + q;
                *(float2*)(As + r0 * 68 + c) =
                    make_float2(acc[i][j][0] + b1s[c], acc[i][j][1] + b1s[c + 1]);
                *(float2*)(As + (r0 + 8) * 68 + c) =
                    make_float2(acc[i][j][2] + b1s[c], acc[i][j][3] + b1s[c + 1]);
            }
        __syncthreads();
#pragma unroll
        for (int i = 0; i < 8; i++) {
            int f = tid + i * 256;
            int r = f >> 4, c4 = f & 15;
            if (row0 + r < N_NODES)
                *(float4*)(out + (size_t)(row0 + r) * 64 + c4 * 4) =
                    *(const float4*)(As + r * 68 + c4 * 4);
        }
        return;
    }

    // T = relu(D + b1) -> As
    __syncthreads();
#pragma unroll
    for (int i = 0; i < 2; i++)
#pragma unroll
        for (int j = 0; j < 4; j++) {
            int c = n0 + 8 * j + 2 * t4;
            int r0 = m0 + 16 * i + q;
            *(float2*)(As + r0 * 68 + c) =
                make_float2(fmaxf(acc[i][j][0] + b1s[c], 0.f),
                            fmaxf(acc[i][j][1] + b1s[c + 1], 0.f));
            *(float2*)(As + (r0 + 8) * 68 + c) =
                make_float2(fmaxf(acc[i][j][2] + b1s[c], 0.f),
                            fmaxf(acc[i][j][3] + b1s[c + 1], 0.f));
        }
    __syncthreads();

    // stage 2: D2 = T @ W2
    float ac2[2][4][4];
#pragma unroll
    for (int i = 0; i < 2; i++)
#pragma unroll
        for (int j = 0; j < 4; j++)
#pragma unroll
            for (int r = 0; r < 4; r++) ac2[i][j][r] = 0.f;

#pragma unroll
    for (int ks = 0; ks < 4; ks++) {
        const int kk = ks * 16;
        uint32_t AH[2][4], AL[2][4];
#pragma unroll
        for (int i = 0; i < 2; i++) {
            const float* ap = As + (m0 + 16 * i + q) * 68 + kk + 2 * t4;
            split_h2(*(const float2*)(ap),              AH[i][0], AL[i][0]);
            split_h2(*(const float2*)(ap + 8 * 68),     AH[i][1], AL[i][1]);
            split_h2(*(const float2*)(ap + 8),          AH[i][2], AL[i][2]);
            split_h2(*(const float2*)(ap + 8 * 68 + 8), AH[i][3], AL[i][3]);
        }
        uint32_t BH[4][2], BL[4][2];
#pragma unroll
        for (int j = 0; j < 4; j++) {
            const float* bp = Wb + (kk + 2 * t4) * 68 + n0 + 8 * j + q;
            split_h2(make_float2(bp[0], bp[68]),          BH[j][0], BL[j][0]);
            split_h2(make_float2(bp[8 * 68], bp[9 * 68]), BH[j][1], BL[j][1]);
        }
#pragma unroll
        for (int i = 0; i < 2; i++)
#pragma unroll
            for (int j = 0; j < 4; j++) {
                mma16(ac2[i][j], AH[i], BH[j]);
                mma16(ac2[i][j], AL[i], BH[j]);
                mma16(ac2[i][j], AH[i], BL[j]);
            }
    }

    // z = relu(D2 + b2) -> stage (zero invalid rows)
    __syncthreads();
#pragma unroll
    for (int i = 0; i < 2; i++)
#pragma unroll
        for (int j = 0; j < 4; j++) {
            int c = n0 + 8 * j + 2 * t4;
            int r0 = m0 + 16 * i + q;
            float2 z0 = make_float2(fmaxf(ac2[i][j][0] + b2s[c], 0.f),
                                    fmaxf(ac2[i][j][1] + b2s[c + 1], 0.f));
            float2 z1 = make_float2(fmaxf(ac2[i][j][2] + b2s[c], 0.f),
                                    fmaxf(ac2[i][j][3] + b2s[c + 1], 0.f));
            if (row0 + r0 >= N_NODES) z0 = make_float2(0.f, 0.f);
            if (row0 + r0 + 8 >= N_NODES) z1 = make_float2(0.f, 0.f);
            *(float2*)(As + r0 * 68 + c) = z0;
            *(float2*)(As + (r0 + 8) * 68 + c) = z1;
        }
    __syncthreads();

    // coalesced STG + BN partials
    float cs0 = 0.f, cs1 = 0.f, cs2 = 0.f, cs3 = 0.f;
    float cq0 = 0.f, cq1 = 0.f, cq2 = 0.f, cq3 = 0.f;
    const int mc4 = tid & 15;
#pragma unroll
    for (int i = 0; i < 8; i++) {
        int f = tid + i * 256;
        int r = f >> 4;
        float4 v = *(const float4*)(As + r * 68 + mc4 * 4);
        cs0 += v.x; cs1 += v.y; cs2 += v.z; cs3 += v.w;
        cq0 += v.x * v.x; cq1 += v.y * v.y; cq2 += v.z * v.z; cq3 += v.w * v.w;
        if (row0 + r < N_NODES)
            *(float4*)(out + (size_t)(row0 + r) * 64 + mc4 * 4) = v;
    }
    atomicAdd(&ssum[mc4 * 4 + 0], cs0);
    atomicAdd(&ssum[mc4 * 4 + 1], cs1);
    atomicAdd(&ssum[mc4 * 4 + 2], cs2);
    atomicAdd(&ssum[mc4 * 4 + 3], cs3);
    atomicAdd(&ssq[mc4 * 4 + 0], cq0);
    atomicAdd(&ssq[mc4 * 4 + 1], cq1);
    atomicAdd(&ssq[mc4 * 4 + 2], cq2);
    atomicAdd(&ssq[mc4 * 4 + 3], cq3);
    __syncthreads();
    if (tid < 64) {
        atomicAdd(bnacc + tid, (double)ssum[tid]);
        atomicAdd(bnacc + 64 + tid, (double)ssq[tid]);
    }
}

// ---------------- pool: g[batch[n]] += BN(z[n]) ------------------------------
__global__ void pool_kernel(const void* __restrict__ batch,
                            const float* __restrict__ zin,
                            const double* __restrict__ acc,
                            const float* __restrict__ gamma,
                            const float* __restrict__ beta)
{
    __shared__ float s_s[64], s_b[64];
    const int tid = threadIdx.x, lane = tid & 31, w = tid >> 5;
    if (tid < 64) {
        double sum = acc[tid], sq = acc[64 + tid];
        float mean = (float)(sum / (double)N_NODES);
        float var = (float)(sq / (double)N_NODES) - mean * mean;
        float sc = gamma[tid] * rsqrtf(var + 1e-5f);
        s_s[tid] = sc;
        s_b[tid] = beta[tid] - mean * sc;
    }
    __syncthreads();
    int node = blockIdx.x * 8 + w;
    if (node >= N_NODES) return;
    const int c0 = lane * 2;
    int b = load_idx(batch, node);
    float2 v = *(const float2*)(zin + (size_t)node * 64 + c0);
    float vx = v.x * s_s[c0] + s_b[c0];
    float vy = v.y * s_s[c0 + 1] + s_b[c0 + 1];
    float* addr = d_g + (size_t)b * 64 + c0;
    asm volatile("red.global.add.v2.f32 [%0], {%1, %2};"
                 :: "l"(addr), "f"(vx), "f"(vy) : "memory");
}

// ---------------- head -------------------------------------------------------
__global__ void head_kernel(const float* __restrict__ W1, const float* __restrict__ b1,
                            const float* __restrict__ W2, const float* __restrict__ b2,
                            float* __restrict__ out)
{
    __shared__ float W1s[64 * 64];
    __shared__ float W2s[64 * 16];
    __shared__ float b1s[64];
    __shared__ float b2s[16];
    int tid = threadIdx.x;
#pragma unroll
    for (int i = 0; i < 16; i++) W1s[tid + i * 256] = W1[tid + i * 256];
#pragma unroll
    for (int i = 0; i < 4; i++) W2s[tid + i * 256] = W2[tid + i * 256];
    if (tid < 64) b1s[tid] = b1[tid];
    if (tid < 16) b2s[tid] = b2[tid];
    __syncthreads();

    int row = blockIdx.x * 256 + tid;
    float gr[64];
#pragma unroll
    for (int k = 0; k < 64; k++) gr[k] = d_g[(size_t)row * 64 + k];
    float oacc[16];
#pragma unroll
    for (int o = 0; o < 16; o++) oacc[o] = b2s[o];

    for (int j = 0; j < 64; j++) {
        float t = b1s[j];
#pragma unroll
        for (int k = 0; k < 64; k++) t += gr[k] * W1s[k * 64 + j];
        t = fmaxf(t, 0.f);
#pragma unroll
        for (int o = 0; o < 16; o++) oacc[o] += t * W2s[j * 16 + o];
    }
#pragma unroll
    for (int o = 0; o < 16; o++) out[(size_t)row * 16 + o] = oacc[o];
}

// =============================================================================
extern "C" void kernel_launch(void* const* d_in, const int* in_sizes, int n_in,
                              void* d_out, int out_size)
{
    const float* x       = (const float*)d_in[0];
    const void*  ei      = d_in[1];
    const void*  batch   = d_in[2];
    const float* enc_W   = (const float*)d_in[3];
    const float* enc_b   = (const float*)d_in[4];
    const float* conv_W1 = (const float*)d_in[5];
    const float* conv_b1 = (const float*)d_in[6];
    const float* conv_W2 = (const float*)d_in[7];
    const float* conv_b2 = (const float*)d_in[8];
    const float* bn_g    = (const float*)d_in[9];
    const float* bn_b    = (const float*)d_in[10];
    const float* fc1_W   = (const float*)d_in[11];
    const float* fc1_b   = (const float*)d_in[12];
    const float* fc2_W   = (const float*)d_in[13];
    const float* fc2_b   = (const float*)d_in[14];
    float* out = (float*)d_out;

    float *h_p, *z_p;
    double* acc_p;
    cudaGetSymbolAddress((void**)&h_p, d_h);
    cudaGetSymbolAddress((void**)&z_p, d_z);
    cudaGetSymbolAddress((void**)&acc_p, d_bnacc);

    cudaFuncSetAttribute(mlp_mma<2, false>,
                         cudaFuncAttributeMaxDynamicSharedMemorySize, SMEM_MMA);
    cudaFuncSetAttribute(mlp_mma<1, true>,
                         cudaFuncAttributeMaxDynamicSharedMemorySize, SMEM_MMA);

    const int EB = (N_EDGES + 255) / 256;          // 3125
    const int WB = (N_NODES + 7) / 8;              // 6250
    const int TB = (N_NODES + 127) / 128;          // 391

    zero_detect_kernel<<<(N_NODES + 255) / 256, 256>>>((const unsigned int*)ei);

    count_kernel<<<EB, 256>>>(ei);
    scan1_kernel<<<N_CHUNKS, SCAN_CHUNK>>>();
    scan23_kernel<<<N_CHUNKS, SCAN_CHUNK>>>();
    fill_kernel<<<EB, 256>>>(ei);

    // encoder: z = x @ enc_W + enc_b
    mlp_mma<2, false><<<TB, 256, SMEM_MMA>>>(x, enc_W, enc_b, nullptr, nullptr,
                                             z_p, nullptr);

    for (int l = 0; l < N_LAYERS; l++) {
        if (l == 0)
            agg_kernel<false><<<WB, 256>>>(z_p, h_p, nullptr, nullptr, nullptr);
        else
            agg_kernel<true><<<WB, 256>>>(z_p, h_p, acc_p + (l - 1) * 128,
                                          bn_g + (l - 1) * 64, bn_b + (l - 1) * 64);
        mlp_mma<1, true><<<TB, 256, SMEM_MMA>>>(h_p, conv_W1 + l * 64 * 64,
                                                conv_b1 + l * 64,
                                                conv_W2 + l * 64 * 64,
                                                conv_b2 + l * 64,
                                                z_p, acc_p + l * 128);
    }

    pool_kernel<<<WB, 256>>>(batch, z_p, acc_p + 4 * 128, bn_g + 4 * 64, bn_b + 4 * 64);
    head_kernel<<<2, 256>>>(fc1_W, fc1_b, fc2_W, fc2_b, out);
}